// round 4
// baseline (speedup 1.0000x reference)
#include <cuda_runtime.h>
#include <cstdint>

// ---------------------------------------------------------------------------
// POS predictor: emb lookup -> gi GEMM (tf32 mma) -> 512-step GRU -> classifier
// B=64, T=512, E=H=1024, 3H=3072, NCLS=20
// ---------------------------------------------------------------------------

#define B_   64
#define T_   512
#define H_   1024
#define G3   3072
#define NC   20
#define NCTA2 128   // persistent recurrence CTAs (1 wave on 148 SMs)
#define SLICE 8     // h-columns per recurrence CTA

typedef unsigned long long u64;

// ------------------------- device scratch (no allocs) ----------------------
__device__ float    g_gi[(long long)T_ * B_ * G3]; // [t*64+b][3H]
__device__ float    g_hT[2][H_ * B_];              // transposed h, double buf
__device__ float    g_hs[(long long)T_ * B_ * H_]; // gru_out [t*64+b][H]
__device__ unsigned g_bar_cnt;
__device__ unsigned g_bar_flag;

// ------------------------- f32x2 helpers -----------------------------------
__device__ __forceinline__ void fma2(u64 &d, u64 a, u64 b) {
    asm("fma.rn.f32x2 %0, %1, %2, %0;" : "+l"(d) : "l"(a), "l"(b));
}
__device__ __forceinline__ u64 add2(u64 a, u64 b) {
    u64 r; asm("add.rn.f32x2 %0, %1, %2;" : "=l"(r) : "l"(a), "l"(b)); return r;
}
__device__ __forceinline__ u64 pack2(float x, float y) {
    u64 r; asm("mov.b64 %0, {%1, %2};" : "=l"(r) : "f"(x), "f"(y)); return r;
}
__device__ __forceinline__ float2 unpack2(u64 v) {
    float2 f; asm("mov.b64 {%0, %1}, %2;" : "=f"(f.x), "=f"(f.y) : "l"(v)); return f;
}
__device__ __forceinline__ uint32_t cvt_tf32(float f) {
    uint32_t r; asm("cvt.rna.tf32.f32 %0, %1;" : "=r"(r) : "f"(f)); return r;
}
__device__ __forceinline__ void mma_tf32(float *d, const uint32_t *a, const uint32_t *b) {
    asm("mma.sync.aligned.m16n8k8.row.col.f32.tf32.tf32.f32 "
        "{%0,%1,%2,%3}, {%4,%5,%6,%7}, {%8,%9}, {%0,%1,%2,%3};"
        : "+f"(d[0]), "+f"(d[1]), "+f"(d[2]), "+f"(d[3])
        : "r"(a[0]), "r"(a[1]), "r"(a[2]), "r"(a[3]), "r"(b[0]), "r"(b[1]));
}
__device__ __forceinline__ void cpa16(uint32_t saddr, const void *g) {
    asm volatile("cp.async.cg.shared.global [%0], [%1], 16;" :: "r"(saddr), "l"(g));
}

// ------------------------- grid-wide barrier (replay-safe) -----------------
__device__ __forceinline__ void grid_sync() {
    __threadfence();
    __syncthreads();
    if (threadIdx.x == 0) {
        unsigned my  = *(volatile unsigned *)&g_bar_flag;
        unsigned arr = atomicAdd(&g_bar_cnt, 1u);
        if (arr == gridDim.x - 1) {
            g_bar_cnt = 0u;
            __threadfence();
            atomicAdd(&g_bar_flag, 1u);   // monotonic: replay-safe
        } else {
            while (*(volatile unsigned *)&g_bar_flag == my) { __nanosleep(64); }
        }
    }
    __syncthreads();
}

// ===========================================================================
// Kernel 1: gi = gather(emb, x) @ w_ih^T + b_ih   via tf32 mma.sync
// BM=128 BN=64 BK=32, 8 warps (4m x 2n), warp tile 32x32 (2x4 m16n8k8 tiles)
// ===========================================================================
__global__ __launch_bounds__(256) void gi_gemm(const int   *__restrict__ x,
                                               const float *__restrict__ emb,
                                               const float *__restrict__ w_ih,
                                               const float *__restrict__ b_ih) {
    __shared__ uint32_t sA[32][132];   // [k][m], pad 4 -> frag loads conflict-free
    __shared__ uint32_t sB[32][68];    // [k][n]
    __shared__ int sTok[128];

    const int tid  = threadIdx.x;
    const int warp = tid >> 5, lane = tid & 31;
    const int g0   = blockIdx.x * 64;
    const int m0   = blockIdx.y * 128;

    if (tid < 128) {
        int m = m0 + tid;                       // m = t*64 + b
        sTok[tid] = x[(m & 63) * T_ + (m >> 6)];
    }
    __syncthreads();

    const int wm = (warp & 3) * 32;             // warp m offset in CTA tile
    const int wn = (warp >> 2) * 32;            // warp n offset
    const int gq = lane >> 2, tg = lane & 3;

    float acc[2][4][4];
#pragma unroll
    for (int i = 0; i < 2; ++i)
#pragma unroll
        for (int j = 0; j < 4; ++j)
#pragma unroll
            for (int q = 0; q < 4; ++q) acc[i][j][q] = 0.f;

    for (int ko = 0; ko < H_; ko += 32) {
        // --- stage A (embedding gather): 128 m x 32 k, 16 floats/thread
        {
            int row = tid >> 1, kb = (tid & 1) * 16;
            const float *src = emb + (long long)sTok[row] * H_ + ko + kb;
#pragma unroll
            for (int i = 0; i < 4; ++i) {
                float4 v = *(const float4 *)(src + 4 * i);
                sA[kb + 4 * i + 0][row] = cvt_tf32(v.x);
                sA[kb + 4 * i + 1][row] = cvt_tf32(v.y);
                sA[kb + 4 * i + 2][row] = cvt_tf32(v.z);
                sA[kb + 4 * i + 3][row] = cvt_tf32(v.w);
            }
        }
        // --- stage B: 64 n x 32 k, 8 floats/thread
        {
            int n = tid >> 2, kb = (tid & 3) * 8;
            const float *src = w_ih + (long long)(g0 + n) * H_ + ko + kb;
#pragma unroll
            for (int i = 0; i < 2; ++i) {
                float4 v = *(const float4 *)(src + 4 * i);
                sB[kb + 4 * i + 0][n] = cvt_tf32(v.x);
                sB[kb + 4 * i + 1][n] = cvt_tf32(v.y);
                sB[kb + 4 * i + 2][n] = cvt_tf32(v.z);
                sB[kb + 4 * i + 3][n] = cvt_tf32(v.w);
            }
        }
        __syncthreads();

#pragma unroll
        for (int ks = 0; ks < 4; ++ks) {
            const int k0 = ks * 8;
            uint32_t a[2][4], b[4][2];
#pragma unroll
            for (int mt = 0; mt < 2; ++mt) {
                int rb = wm + mt * 16 + gq;
                a[mt][0] = sA[k0 + tg][rb];
                a[mt][1] = sA[k0 + tg][rb + 8];
                a[mt][2] = sA[k0 + tg + 4][rb];
                a[mt][3] = sA[k0 + tg + 4][rb + 8];
            }
#pragma unroll
            for (int nt = 0; nt < 4; ++nt) {
                int cb = wn + nt * 8 + gq;
                b[nt][0] = sB[k0 + tg][cb];
                b[nt][1] = sB[k0 + tg + 4][cb];
            }
#pragma unroll
            for (int mt = 0; mt < 2; ++mt)
#pragma unroll
                for (int nt = 0; nt < 4; ++nt)
                    mma_tf32(acc[mt][nt], a[mt], b[nt]);
        }
        __syncthreads();
    }

    // --- epilogue: D row = m0+wm+mt*16+gq(+8), col = g0+wn+nt*8+tg*2(+1)
#pragma unroll
    for (int mt = 0; mt < 2; ++mt) {
#pragma unroll
        for (int nt = 0; nt < 4; ++nt) {
            int n  = g0 + wn + nt * 8 + tg * 2;
            float2 bias = *(const float2 *)(b_ih + n);
            int ma = m0 + wm + mt * 16 + gq;
            float2 o0 = {acc[mt][nt][0] + bias.x, acc[mt][nt][1] + bias.y};
            float2 o1 = {acc[mt][nt][2] + bias.x, acc[mt][nt][3] + bias.y};
            *(float2 *)(g_gi + (long long)ma * G3 + n)       = o0;
            *(float2 *)(g_gi + (long long)(ma + 8) * G3 + n) = o1;
        }
    }
}

// ===========================================================================
// Kernel 2: persistent GRU recurrence, h staged via cp.async into SMEM.
// 128 CTAs x 256 thr. CTA owns 24 w_hh rows (SMEM-resident). h transposed
// [k][b]. Thread: tid = og*64 + bg*4 + kq -> 6 outputs x 4 batches x K/4.
// split-K reduced via __shfl_xor over adjacent lanes (kq in low 2 bits).
// ===========================================================================
#define KC      128                               // k chunk
#define SM2_W   (24 * 1024 * 4)                   // 98304 B  weights
#define SM2_H   (2 * KC * 64 * 4)                 // 65536 B  h double buf
#define SM2_GH  (24 * 64 * 4)                     // 6144 B
#define SM2_TOT (SM2_W + SM2_H + SM2_GH + 128)

__global__ __launch_bounds__(256, 1) void gru_rec(const float *__restrict__ w_hh,
                                                  const float *__restrict__ b_hh) {
    extern __shared__ __align__(16) char smem[];
    float *sW   = (float *)smem;                          // [24][1024]
    float *sH   = (float *)(smem + SM2_W);                // [2][KC][64]
    float *sGh  = (float *)(smem + SM2_W + SM2_H);        // [24][64]
    float *sBhh = (float *)(smem + SM2_W + SM2_H + SM2_GH);

    const int tid = threadIdx.x;
    const int c0  = blockIdx.x * SLICE;

    // weights -> SMEM (persistent across all 512 steps)
    for (int i = tid; i < 24 * 256; i += 256) {
        int o = i >> 8, kk = (i & 255) << 2;
        int g = o >> 3, j = o & 7;
        float4 v = *(const float4 *)(w_hh + (long long)(g * H_ + c0 + j) * H_ + kk);
        *(float4 *)(sW + o * 1024 + kk) = v;
    }
    if (tid < 24) sBhh[tid] = b_hh[(tid >> 3) * H_ + c0 + (tid & 7)];

    // zero h buffer 0 (every launch/replay)
    for (int i = tid; i < SLICE * B_; i += 256) {
        int c = i >> 6, b = i & 63;
        g_hT[0][(c0 + c) * B_ + b] = 0.f;
    }
    grid_sync();

    const int og = tid >> 6;           // 0..3  output group (6 rows)
    const int bg = (tid >> 2) & 15;    // 0..15 batch group (4 batches)
    const int kq = tid & 3;            // 0..3  split-K lane (adjacent!)
    const float *wb = sW + og * 6 * 1024;

    const uint32_t sH_base = (uint32_t)__cvta_generic_to_shared(sH);

    for (int t = 0; t < T_; ++t) {
        const float *hbuf = g_hT[t & 1];
        float       *hout = g_hT[(t & 1) ^ 1];

        // prefetch gi for the pointwise phase
        float gia[3], gib[3];
        {
            int c = tid >> 6, b = tid & 63;
            const float *p = g_gi + (long long)(t * B_ + b) * G3 + c0 + c;
            gia[0] = __ldg(p); gia[1] = __ldg(p + H_); gia[2] = __ldg(p + 2 * H_);
            int idx = tid + 256; c = idx >> 6; b = idx & 63;
            p = g_gi + (long long)(t * B_ + b) * G3 + c0 + c;
            gib[0] = __ldg(p); gib[1] = __ldg(p + H_); gib[2] = __ldg(p + 2 * H_);
        }

        u64 acc[6][2];
#pragma unroll
        for (int o = 0; o < 6; ++o) { acc[o][0] = 0ull; acc[o][1] = 0ull; }

        // stage chunk 0
        {
            const char *src = (const char *)hbuf;
#pragma unroll
            for (int j = 0; j < 8; ++j) {
                int off = (tid + j * 256) * 16;
                cpa16(sH_base + off, src + off);
            }
            asm volatile("cp.async.commit_group;");
        }

        for (int ch = 0; ch < 8; ++ch) {
            if (ch < 7) {
                const char *src = (const char *)hbuf + (ch + 1) * KC * 64 * 4;
                uint32_t dst = sH_base + ((ch + 1) & 1) * KC * 64 * 4;
#pragma unroll
                for (int j = 0; j < 8; ++j) {
                    int off = (tid + j * 256) * 16;
                    cpa16(dst + off, src + off);
                }
                asm volatile("cp.async.commit_group;");
                asm volatile("cp.async.wait_group 1;");
            } else {
                asm volatile("cp.async.wait_group 0;");
            }
            __syncthreads();

            const float *hs = sH + (ch & 1) * KC * 64;
            const int kbase = ch * KC + kq * 32;
#pragma unroll 4
            for (int i = 0; i < 16; ++i) {      // k pairs
                int kl = kq * 32 + 2 * i;
                ulonglong2 h0 = *(const ulonglong2 *)(hs + kl * 64 + bg * 4);
                ulonglong2 h1 = *(const ulonglong2 *)(hs + (kl + 1) * 64 + bg * 4);
                int kgl = kbase + 2 * i;
#pragma unroll
                for (int o = 0; o < 6; ++o) {
                    float2 wv = *(const float2 *)(wb + o * 1024 + kgl);
                    u64 w0 = pack2(wv.x, wv.x), w1 = pack2(wv.y, wv.y);
                    fma2(acc[o][0], w0, h0.x);
                    fma2(acc[o][1], w0, h0.y);
                    fma2(acc[o][0], w1, h1.x);
                    fma2(acc[o][1], w1, h1.y);
                }
            }
            __syncthreads();
        }

        // split-K reduce over kq (lanes xor 1, 2)
#pragma unroll
        for (int o = 0; o < 6; ++o) {
            acc[o][0] = add2(acc[o][0], __shfl_xor_sync(0xffffffffu, acc[o][0], 1));
            acc[o][1] = add2(acc[o][1], __shfl_xor_sync(0xffffffffu, acc[o][1], 1));
            acc[o][0] = add2(acc[o][0], __shfl_xor_sync(0xffffffffu, acc[o][0], 2));
            acc[o][1] = add2(acc[o][1], __shfl_xor_sync(0xffffffffu, acc[o][1], 2));
        }
        if (kq == 0) {
#pragma unroll
            for (int o = 0; o < 6; ++o) {
                float2 p0 = unpack2(acc[o][0]);
                float2 p1 = unpack2(acc[o][1]);
                float4 v; v.x = p0.x; v.y = p0.y; v.z = p1.x; v.w = p1.y;
                *(float4 *)(sGh + (og * 6 + o) * 64 + bg * 4) = v;
            }
        }
        __syncthreads();

        // pointwise gate math: 512 (c,b) cells, 2 per thread
#pragma unroll
        for (int half = 0; half < 2; ++half) {
            int idx = tid + half * 256;
            int c = idx >> 6, b = idx & 63;
            const float *gi = half ? gib : gia;
            float ghr = sGh[(c)      * 64 + b] + sBhh[c];
            float ghz = sGh[(8 + c)  * 64 + b] + sBhh[8 + c];
            float ghn = sGh[(16 + c) * 64 + b] + sBhh[16 + c];
            float r = 1.f / (1.f + __expf(-(gi[0] + ghr)));
            float z = 1.f / (1.f + __expf(-(gi[1] + ghz)));
            float n = tanhf(gi[2] + r * ghn);
            float hp;
            asm volatile("ld.global.cg.f32 %0, [%1];"
                         : "=f"(hp) : "l"(hbuf + (c0 + c) * B_ + b));
            float hn = (1.f - z) * n + z * hp;
            hout[(c0 + c) * B_ + b] = hn;
            g_hs[(long long)(t * B_ + b) * H_ + c0 + c] = hn;
        }

        grid_sync();
    }
}

// ===========================================================================
// Kernel 3: classifier  pred = g_hs @ cls_w^T + cls_b
// ===========================================================================
#define SM3_TOT (1024 * 20 * 4 + 128)

__global__ __launch_bounds__(256) void cls_gemm(const float *__restrict__ cls_w,
                                                const float *__restrict__ cls_b,
                                                float *__restrict__ out) {
    extern __shared__ __align__(16) char sm3[];
    float *sWc   = (float *)sm3;            // [1024][20] k-major
    float *sBias = sWc + 1024 * 20;

    const int tid = threadIdx.x;
    for (int i = tid; i < 1024 * 20; i += 256) {
        int c = i / 1024, k = i - c * 1024;
        sWc[k * 20 + c] = cls_w[i];
    }
    if (tid < 20) sBias[tid] = cls_b[tid];
    __syncthreads();

    const int tokl = tid >> 2, kq = tid & 3;
    const int token = blockIdx.x * 64 + tokl;
    const float *hrow = g_hs + (long long)token * H_ + kq * 256;

    u64 acc[10];
#pragma unroll
    for (int c = 0; c < 10; ++c) acc[c] = 0ull;

    for (int k = 0; k < 256; k += 4) {
        float4 hv = *(const float4 *)(hrow + k);
        float hs4[4] = {hv.x, hv.y, hv.z, hv.w};
#pragma unroll
        for (int i = 0; i < 4; ++i) {
            u64 h2 = pack2(hs4[i], hs4[i]);
            const u64 *wr = (const u64 *)(sWc + (kq * 256 + k + i) * 20);
#pragma unroll
            for (int c = 0; c < 10; ++c) fma2(acc[c], h2, wr[c]);
        }
    }
#pragma unroll
    for (int c = 0; c < 10; ++c) {
        acc[c] = add2(acc[c], __shfl_xor_sync(0xffffffffu, acc[c], 1));
        acc[c] = add2(acc[c], __shfl_xor_sync(0xffffffffu, acc[c], 2));
    }
    if (kq == 0) {
        int t = token >> 6, b = token & 63;
        float *op = out + (long long)(b * T_ + t) * NC;
#pragma unroll
        for (int c = 0; c < 10; ++c) {
            float2 p = unpack2(acc[c]);
            op[2 * c]     = p.x + sBias[2 * c];
            op[2 * c + 1] = p.y + sBias[2 * c + 1];
        }
    }
}

// ===========================================================================
extern "C" void kernel_launch(void *const *d_in, const int *in_sizes, int n_in,
                              void *d_out, int out_size) {
    const int   *x     = (const int *)d_in[0];
    const float *emb   = (const float *)d_in[1];
    const float *w_ih  = (const float *)d_in[2];
    const float *w_hh  = (const float *)d_in[3];
    const float *b_ih  = (const float *)d_in[4];
    const float *b_hh  = (const float *)d_in[5];
    const float *cls_w = (const float *)d_in[6];
    const float *cls_b = (const float *)d_in[7];
    float *out = (float *)d_out;

    cudaFuncSetAttribute(gru_rec, cudaFuncAttributeMaxDynamicSharedMemorySize, SM2_TOT);
    cudaFuncSetAttribute(cls_gemm, cudaFuncAttributeMaxDynamicSharedMemorySize, SM3_TOT);

    dim3 g1(G3 / 64, (T_ * B_) / 128);          // (48, 256)
    gi_gemm<<<g1, 256>>>(x, emb, w_ih, b_ih);
    gru_rec<<<NCTA2, 256, SM2_TOT>>>(w_hh, b_hh);
    cls_gemm<<<(T_ * B_) / 64, 256, SM3_TOT>>>(cls_w, cls_b, out);
}

// round 5
// speedup vs baseline: 2.4990x; 2.4990x over previous
#include <cuda_runtime.h>
#include <cstdint>

// ---------------------------------------------------------------------------
// POS predictor: emb lookup -> gi GEMM (tf32 mma) -> 512-step GRU -> classifier
// B=64, T=512, E=H=1024, 3H=3072, NCLS=20
// ---------------------------------------------------------------------------

#define B_   64
#define T_   512
#define H_   1024
#define G3   3072
#define NC   20
#define NCTA2 128   // persistent recurrence CTAs (1 wave on 148 SMs)
#define SLICE 8     // h-columns per recurrence CTA

typedef unsigned long long u64;

// ------------------------- device scratch (no allocs) ----------------------
__device__ float    g_gi[(long long)T_ * B_ * G3]; // [t*64+b][3H]
__device__ float    g_hT[2][H_ * B_];              // transposed h, double buf
__device__ float    g_hs[(long long)T_ * B_ * H_]; // gru_out [t*64+b][H]
__device__ unsigned g_bar_cnt;
__device__ unsigned g_bar_flag;

// ------------------------- f32x2 helpers -----------------------------------
__device__ __forceinline__ void fma2(u64 &d, u64 a, u64 b) {
    asm("fma.rn.f32x2 %0, %1, %2, %0;" : "+l"(d) : "l"(a), "l"(b));
}
__device__ __forceinline__ u64 add2(u64 a, u64 b) {
    u64 r; asm("add.rn.f32x2 %0, %1, %2;" : "=l"(r) : "l"(a), "l"(b)); return r;
}
__device__ __forceinline__ u64 pack2(float x, float y) {
    u64 r; asm("mov.b64 %0, {%1, %2};" : "=l"(r) : "f"(x), "f"(y)); return r;
}
__device__ __forceinline__ float2 unpack2(u64 v) {
    float2 f; asm("mov.b64 {%0, %1}, %2;" : "=f"(f.x), "=f"(f.y) : "l"(v)); return f;
}
__device__ __forceinline__ uint32_t cvt_tf32(float f) {
    uint32_t r; asm("cvt.rna.tf32.f32 %0, %1;" : "=r"(r) : "f"(f)); return r;
}
__device__ __forceinline__ void mma_tf32(float *d, const uint32_t *a, const uint32_t *b) {
    asm("mma.sync.aligned.m16n8k8.row.col.f32.tf32.tf32.f32 "
        "{%0,%1,%2,%3}, {%4,%5,%6,%7}, {%8,%9}, {%0,%1,%2,%3};"
        : "+f"(d[0]), "+f"(d[1]), "+f"(d[2]), "+f"(d[3])
        : "r"(a[0]), "r"(a[1]), "r"(a[2]), "r"(a[3]), "r"(b[0]), "r"(b[1]));
}
__device__ __forceinline__ void cpa16(uint32_t saddr, const void *g) {
    asm volatile("cp.async.cg.shared.global [%0], [%1], 16;" :: "r"(saddr), "l"(g));
}

// ------------------------- grid-wide barrier (replay-safe) -----------------
__device__ __forceinline__ void grid_sync() {
    __threadfence();
    __syncthreads();
    if (threadIdx.x == 0) {
        unsigned my  = *(volatile unsigned *)&g_bar_flag;
        unsigned arr = atomicAdd(&g_bar_cnt, 1u);
        if (arr == gridDim.x - 1) {
            g_bar_cnt = 0u;
            __threadfence();
            atomicAdd(&g_bar_flag, 1u);   // monotonic: replay-safe
        } else {
            while (*(volatile unsigned *)&g_bar_flag == my) { __nanosleep(64); }
        }
    }
    __syncthreads();
}

// ===========================================================================
// Kernel 1: gi = gather(emb, x) @ w_ih^T + b_ih   via tf32 mma.sync
// BM=128 BN=64 BK=32, 8 warps (4m x 2n), warp tile 32x32 (2x4 m16n8k8 tiles)
// Pads chosen so row stride = 32 mod 128 B -> frag loads conflict-free:
// bank byte = tg*32 + gq*4 (+64*mt), distinct for all 32 lanes.
// ===========================================================================
#define PAD_A 136
#define PAD_B 72

__global__ __launch_bounds__(256) void gi_gemm(const int   *__restrict__ x,
                                               const float *__restrict__ emb,
                                               const float *__restrict__ w_ih,
                                               const float *__restrict__ b_ih) {
    __shared__ uint32_t sA[32][PAD_A];
    __shared__ uint32_t sB[32][PAD_B];
    __shared__ int sTok[128];

    const int tid  = threadIdx.x;
    const int warp = tid >> 5, lane = tid & 31;
    const int g0   = blockIdx.x * 64;
    const int m0   = blockIdx.y * 128;

    if (tid < 128) {
        int m = m0 + tid;                       // m = t*64 + b
        sTok[tid] = x[(m & 63) * T_ + (m >> 6)];
    }
    __syncthreads();

    const int wm = (warp & 3) * 32;             // warp m offset in CTA tile
    const int wn = (warp >> 2) * 32;            // warp n offset
    const int gq = lane >> 2, tg = lane & 3;

    float acc[2][4][4];
#pragma unroll
    for (int i = 0; i < 2; ++i)
#pragma unroll
        for (int j = 0; j < 4; ++j)
#pragma unroll
            for (int q = 0; q < 4; ++q) acc[i][j][q] = 0.f;

    for (int ko = 0; ko < H_; ko += 32) {
        // --- stage A (embedding gather): 128 m x 32 k, 16 floats/thread
        {
            int row = tid >> 1, kb = (tid & 1) * 16;
            const float *src = emb + (long long)sTok[row] * H_ + ko + kb;
#pragma unroll
            for (int i = 0; i < 4; ++i) {
                float4 v = *(const float4 *)(src + 4 * i);
                sA[kb + 4 * i + 0][row] = cvt_tf32(v.x);
                sA[kb + 4 * i + 1][row] = cvt_tf32(v.y);
                sA[kb + 4 * i + 2][row] = cvt_tf32(v.z);
                sA[kb + 4 * i + 3][row] = cvt_tf32(v.w);
            }
        }
        // --- stage B: 64 n x 32 k, 8 floats/thread
        {
            int n = tid >> 2, kb = (tid & 3) * 8;
            const float *src = w_ih + (long long)(g0 + n) * H_ + ko + kb;
#pragma unroll
            for (int i = 0; i < 2; ++i) {
                float4 v = *(const float4 *)(src + 4 * i);
                sB[kb + 4 * i + 0][n] = cvt_tf32(v.x);
                sB[kb + 4 * i + 1][n] = cvt_tf32(v.y);
                sB[kb + 4 * i + 2][n] = cvt_tf32(v.z);
                sB[kb + 4 * i + 3][n] = cvt_tf32(v.w);
            }
        }
        __syncthreads();

#pragma unroll
        for (int ks = 0; ks < 4; ++ks) {
            const int k0 = ks * 8;
            uint32_t a[2][4], b[4][2];
#pragma unroll
            for (int mt = 0; mt < 2; ++mt) {
                int rb = wm + mt * 16 + gq;
                a[mt][0] = sA[k0 + tg][rb];
                a[mt][1] = sA[k0 + tg][rb + 8];
                a[mt][2] = sA[k0 + tg + 4][rb];
                a[mt][3] = sA[k0 + tg + 4][rb + 8];
            }
#pragma unroll
            for (int nt = 0; nt < 4; ++nt) {
                int cb = wn + nt * 8 + gq;
                b[nt][0] = sB[k0 + tg][cb];
                b[nt][1] = sB[k0 + tg + 4][cb];
            }
#pragma unroll
            for (int mt = 0; mt < 2; ++mt)
#pragma unroll
                for (int nt = 0; nt < 4; ++nt)
                    mma_tf32(acc[mt][nt], a[mt], b[nt]);
        }
        __syncthreads();
    }

    // --- epilogue
#pragma unroll
    for (int mt = 0; mt < 2; ++mt) {
#pragma unroll
        for (int nt = 0; nt < 4; ++nt) {
            int n  = g0 + wn + nt * 8 + tg * 2;
            float2 bias = *(const float2 *)(b_ih + n);
            int ma = m0 + wm + mt * 16 + gq;
            float2 o0 = {acc[mt][nt][0] + bias.x, acc[mt][nt][1] + bias.y};
            float2 o1 = {acc[mt][nt][2] + bias.x, acc[mt][nt][3] + bias.y};
            *(float2 *)(g_gi + (long long)ma * G3 + n)       = o0;
            *(float2 *)(g_gi + (long long)(ma + 8) * G3 + n) = o1;
        }
    }
}

// ===========================================================================
// Kernel 2: persistent GRU recurrence, h staged via cp.async into SMEM.
// 128 CTAs x 256 thr. CTA owns 24 w_hh rows (SMEM-resident). h transposed
// [k][b]. Thread map: tid = kq*64 + og*16 + bg  -> kq WARP-UNIFORM (no bank
// conflicts: h LDS.128 = 16 distinct 16B segs + broadcast; w loads broadcast).
// Each kq takes rows [kq*32, kq*32+32) of every staged 128-row chunk.
// Split-K reduced via SMEM (once per step).
// ===========================================================================
#define KC      128                               // k chunk (rows)
#define SM2_W   (24 * 1024 * 4)                   // 98304 B  weights
#define SM2_H   (2 * KC * 64 * 4)                 // 65536 B  h double buf
#define SM2_RED (4 * 24 * 16 * 16)                // 24576 B  split-K partials
#define SM2_GH  (24 * 64 * 4)                     // 6144 B
#define SM2_TOT (SM2_W + SM2_H + SM2_RED + SM2_GH + 128)

__global__ __launch_bounds__(256, 1) void gru_rec(const float *__restrict__ w_hh,
                                                  const float *__restrict__ b_hh) {
    extern __shared__ __align__(16) char smem[];
    float      *sW   = (float *)smem;                              // [24][1024]
    float      *sH   = (float *)(smem + SM2_W);                    // [2][KC][64]
    ulonglong2 *sRed = (ulonglong2 *)(smem + SM2_W + SM2_H);       // [4][24][16]
    float      *sGh  = (float *)(smem + SM2_W + SM2_H + SM2_RED);  // [24][64]
    float      *sBhh = (float *)(smem + SM2_W + SM2_H + SM2_RED + SM2_GH);

    const int tid = threadIdx.x;
    const int c0  = blockIdx.x * SLICE;

    // weights -> SMEM (persistent across all 512 steps)
    for (int i = tid; i < 24 * 256; i += 256) {
        int o = i >> 8, kk = (i & 255) << 2;
        int g = o >> 3, j = o & 7;
        float4 v = *(const float4 *)(w_hh + (long long)(g * H_ + c0 + j) * H_ + kk);
        *(float4 *)(sW + o * 1024 + kk) = v;
    }
    if (tid < 24) sBhh[tid] = b_hh[(tid >> 3) * H_ + c0 + (tid & 7)];

    // zero h buffer 0 (every launch/replay)
    for (int i = tid; i < SLICE * B_; i += 256) {
        int c = i >> 6, b = i & 63;
        g_hT[0][(c0 + c) * B_ + b] = 0.f;
    }
    grid_sync();

    const int kq = tid >> 6;           // 0..3  split-K quarter (WARP-UNIFORM)
    const int og = (tid >> 4) & 3;     // 0..3  output group (6 rows)
    const int bg = tid & 15;           // 0..15 batch group (4 batches)
    const float *wb = sW + og * 6 * 1024;

    const uint32_t sH_base = (uint32_t)__cvta_generic_to_shared(sH);

    for (int t = 0; t < T_; ++t) {
        const float *hbuf = g_hT[t & 1];
        float       *hout = g_hT[(t & 1) ^ 1];

        // prefetch gi for the pointwise phase
        float gia[3], gib[3];
        {
            int c = tid >> 6, b = tid & 63;
            const float *p = g_gi + (long long)(t * B_ + b) * G3 + c0 + c;
            gia[0] = __ldg(p); gia[1] = __ldg(p + H_); gia[2] = __ldg(p + 2 * H_);
            int idx = tid + 256; c = idx >> 6; b = idx & 63;
            p = g_gi + (long long)(t * B_ + b) * G3 + c0 + c;
            gib[0] = __ldg(p); gib[1] = __ldg(p + H_); gib[2] = __ldg(p + 2 * H_);
        }

        u64 acc[6][2];
#pragma unroll
        for (int o = 0; o < 6; ++o) { acc[o][0] = 0ull; acc[o][1] = 0ull; }

        // stage chunk 0
        {
            const char *src = (const char *)hbuf;
#pragma unroll
            for (int j = 0; j < 8; ++j) {
                int off = (tid + j * 256) * 16;
                cpa16(sH_base + off, src + off);
            }
            asm volatile("cp.async.commit_group;");
        }

        for (int ch = 0; ch < 8; ++ch) {
            if (ch < 7) {
                const char *src = (const char *)hbuf + (ch + 1) * KC * 64 * 4;
                uint32_t dst = sH_base + ((ch + 1) & 1) * KC * 64 * 4;
#pragma unroll
                for (int j = 0; j < 8; ++j) {
                    int off = (tid + j * 256) * 16;
                    cpa16(dst + off, src + off);
                }
                asm volatile("cp.async.commit_group;");
                asm volatile("cp.async.wait_group 1;");
            } else {
                asm volatile("cp.async.wait_group 0;");
            }
            __syncthreads();

            // this kq works rows [kq*32, kq*32+32) of the chunk
            const float *hs = sH + (ch & 1) * KC * 64 + kq * 32 * 64;
            const int kgl0 = ch * KC + kq * 32;    // global k of row 0
#pragma unroll 4
            for (int i = 0; i < 16; ++i) {         // 2 k per iter
                int kl = 2 * i;
                ulonglong2 h0 = *(const ulonglong2 *)(hs + kl * 64 + bg * 4);
                ulonglong2 h1 = *(const ulonglong2 *)(hs + (kl + 1) * 64 + bg * 4);
                int kgl = kgl0 + kl;
#pragma unroll
                for (int o = 0; o < 6; ++o) {
                    float2 wv = *(const float2 *)(wb + o * 1024 + kgl);
                    u64 w0 = pack2(wv.x, wv.x), w1 = pack2(wv.y, wv.y);
                    fma2(acc[o][0], w0, h0.x);
                    fma2(acc[o][1], w0, h0.y);
                    fma2(acc[o][0], w1, h1.x);
                    fma2(acc[o][1], w1, h1.y);
                }
            }
            __syncthreads();
        }

        // --- split-K reduction (SMEM round-trip, once per step)
#pragma unroll
        for (int o = 0; o < 6; ++o)
            sRed[(kq * 24 + og * 6 + o) * 16 + bg] =
                make_ulonglong2(acc[o][0], acc[o][1]);
        __syncthreads();
        if (tid < 64) {
            int bg2 = tid & 15, og2 = tid >> 4;
#pragma unroll
            for (int o = 0; o < 6; ++o) {
                int row = og2 * 6 + o;
                ulonglong2 r0 = sRed[(0 * 24 + row) * 16 + bg2];
                ulonglong2 r1 = sRed[(1 * 24 + row) * 16 + bg2];
                ulonglong2 r2 = sRed[(2 * 24 + row) * 16 + bg2];
                ulonglong2 r3 = sRed[(3 * 24 + row) * 16 + bg2];
                u64 sx = add2(add2(r0.x, r1.x), add2(r2.x, r3.x));
                u64 sy = add2(add2(r0.y, r1.y), add2(r2.y, r3.y));
                float2 a = unpack2(sx), b2 = unpack2(sy);
                float4 v; v.x = a.x; v.y = a.y; v.z = b2.x; v.w = b2.y;
                *(float4 *)(sGh + row * 64 + bg2 * 4) = v;
            }
        }
        __syncthreads();

        // pointwise gate math: 512 (c,b) cells, 2 per thread
#pragma unroll
        for (int half = 0; half < 2; ++half) {
            int idx = tid + half * 256;
            int c = idx >> 6, b = idx & 63;
            const float *gi = half ? gib : gia;
            float ghr = sGh[(c)      * 64 + b] + sBhh[c];
            float ghz = sGh[(8 + c)  * 64 + b] + sBhh[8 + c];
            float ghn = sGh[(16 + c) * 64 + b] + sBhh[16 + c];
            float r = 1.f / (1.f + __expf(-(gi[0] + ghr)));
            float z = 1.f / (1.f + __expf(-(gi[1] + ghz)));
            float n = tanhf(gi[2] + r * ghn);
            float hp;
            asm volatile("ld.global.cg.f32 %0, [%1];"
                         : "=f"(hp) : "l"(hbuf + (c0 + c) * B_ + b));
            float hn = (1.f - z) * n + z * hp;
            hout[(c0 + c) * B_ + b] = hn;
            g_hs[(long long)(t * B_ + b) * H_ + c0 + c] = hn;
        }

        grid_sync();
    }
}

// ===========================================================================
// Kernel 3: classifier  pred = g_hs @ cls_w^T + cls_b
// ===========================================================================
#define SM3_TOT (1024 * 20 * 4 + 128)

__global__ __launch_bounds__(256) void cls_gemm(const float *__restrict__ cls_w,
                                                const float *__restrict__ cls_b,
                                                float *__restrict__ out) {
    extern __shared__ __align__(16) char sm3[];
    float *sWc   = (float *)sm3;            // [1024][20] k-major
    float *sBias = sWc + 1024 * 20;

    const int tid = threadIdx.x;
    for (int i = tid; i < 1024 * 20; i += 256) {
        int c = i / 1024, k = i - c * 1024;
        sWc[k * 20 + c] = cls_w[i];
    }
    if (tid < 20) sBias[tid] = cls_b[tid];
    __syncthreads();

    const int tokl = tid >> 2, kq = tid & 3;
    const int token = blockIdx.x * 64 + tokl;
    const float *hrow = g_hs + (long long)token * H_ + kq * 256;

    u64 acc[10];
#pragma unroll
    for (int c = 0; c < 10; ++c) acc[c] = 0ull;

    for (int k = 0; k < 256; k += 4) {
        float4 hv = *(const float4 *)(hrow + k);
        float hs4[4] = {hv.x, hv.y, hv.z, hv.w};
#pragma unroll
        for (int i = 0; i < 4; ++i) {
            u64 h2 = pack2(hs4[i], hs4[i]);
            const u64 *wr = (const u64 *)(sWc + (kq * 256 + k + i) * 20);
#pragma unroll
            for (int c = 0; c < 10; ++c) fma2(acc[c], h2, wr[c]);
        }
    }
#pragma unroll
    for (int c = 0; c < 10; ++c) {
        acc[c] = add2(acc[c], __shfl_xor_sync(0xffffffffu, acc[c], 1));
        acc[c] = add2(acc[c], __shfl_xor_sync(0xffffffffu, acc[c], 2));
    }
    if (kq == 0) {
        int t = token >> 6, b = token & 63;
        float *op = out + (long long)(b * T_ + t) * NC;
#pragma unroll
        for (int c = 0; c < 10; ++c) {
            float2 p = unpack2(acc[c]);
            op[2 * c]     = p.x + sBias[2 * c];
            op[2 * c + 1] = p.y + sBias[2 * c + 1];
        }
    }
}

// ===========================================================================
extern "C" void kernel_launch(void *const *d_in, const int *in_sizes, int n_in,
                              void *d_out, int out_size) {
    const int   *x     = (const int *)d_in[0];
    const float *emb   = (const float *)d_in[1];
    const float *w_ih  = (const float *)d_in[2];
    const float *w_hh  = (const float *)d_in[3];
    const float *b_ih  = (const float *)d_in[4];
    const float *b_hh  = (const float *)d_in[5];
    const float *cls_w = (const float *)d_in[6];
    const float *cls_b = (const float *)d_in[7];
    float *out = (float *)d_out;

    cudaFuncSetAttribute(gru_rec, cudaFuncAttributeMaxDynamicSharedMemorySize, SM2_TOT);
    cudaFuncSetAttribute(cls_gemm, cudaFuncAttributeMaxDynamicSharedMemorySize, SM3_TOT);

    dim3 g1(G3 / 64, (T_ * B_) / 128);          // (48, 256)
    gi_gemm<<<g1, 256>>>(x, emb, w_ih, b_ih);
    gru_rec<<<NCTA2, 256, SM2_TOT>>>(w_hh, b_hh);
    cls_gemm<<<(T_ * B_) / 64, 256, SM3_TOT>>>(cls_w, cls_b, out);
}